// round 2
// baseline (speedup 1.0000x reference)
#include <cuda_runtime.h>
#include <math.h>

#define NB 64
#define TT 1024
#define DD 1024
#define HH 1024
#define K4 4096
#define NCTA 128

// Scratch (device globals: no allocations allowed in kernel_launch)
__device__ float g_xW[(size_t)TT * K4 * NB];   // [t][k][n], 1 GiB
__device__ float g_h[2][HH * NB];              // ping-pong [buf][j][n]
__device__ float g_c[HH * NB];                 // [j][n]

// global barrier state
__device__ unsigned int g_bar_count;
__device__ unsigned int g_bar_gen;

__device__ __forceinline__ float sigmoidf_(float v) {
    return 1.0f / (1.0f + expf(-v));
}

// ---------------------------------------------------------------------------
// Phase 1: g_xW[t][k][n] = sum_d x[n][t][d] * Wx[d][k] + b[k]
// ---------------------------------------------------------------------------
__global__ __launch_bounds__(256, 2) void phase1_kernel(
    const float* __restrict__ x, const float* __restrict__ Wx,
    const float* __restrict__ b)
{
    const int cb = blockIdx.x * 32;   // column block (k)
    const int t  = blockIdx.y;

    __shared__ float xs[2][32 * 68];  // [buf][dd*68 + n]  (transposed x tile)
    __shared__ float ws[2][32 * 32];  // [buf][dd*32 + cc]

    const int tid = threadIdx.x;
    const int w = tid >> 5;
    const int l = tid & 31;

    const int ln  = tid >> 2;
    const int ld0 = (tid & 3) * 8;
    const float* xp = x + ((size_t)ln * TT + t) * DD + ld0;

    const int wd = tid >> 3;
    const int wc = (tid & 7) * 4;
    const float* wp = Wx + (size_t)wd * K4 + cb + wc;

    float acc[2][4] = {{0.f,0.f,0.f,0.f},{0.f,0.f,0.f,0.f}};

    float4 rx0, rx1, rw;
    rx0 = *(const float4*)(xp);
    rx1 = *(const float4*)(xp + 4);
    rw  = *(const float4*)(wp);
    {
        float vx[8] = {rx0.x, rx0.y, rx0.z, rx0.w, rx1.x, rx1.y, rx1.z, rx1.w};
        #pragma unroll
        for (int i = 0; i < 8; i++) xs[0][(ld0 + i) * 68 + ln] = vx[i];
        *(float4*)&ws[0][wd * 32 + wc] = rw;
    }
    __syncthreads();

    for (int c = 0; c < 32; c++) {
        const int bb = c & 1;
        if (c < 31) {
            rx0 = *(const float4*)(xp + (c + 1) * 32);
            rx1 = *(const float4*)(xp + (c + 1) * 32 + 4);
            rw  = *(const float4*)(wp + (size_t)(c + 1) * 32 * K4);
        }
        #pragma unroll
        for (int kk = 0; kk < 32; kk++) {
            float2 hv = *(const float2*)&xs[bb][kk * 68 + 2 * l];
            float4 wv = *(const float4*)&ws[bb][kk * 32 + 4 * w];
            acc[0][0] += hv.x * wv.x; acc[0][1] += hv.x * wv.y;
            acc[0][2] += hv.x * wv.z; acc[0][3] += hv.x * wv.w;
            acc[1][0] += hv.y * wv.x; acc[1][1] += hv.y * wv.y;
            acc[1][2] += hv.y * wv.z; acc[1][3] += hv.y * wv.w;
        }
        if (c < 31) {
            __syncthreads();
            float vx[8] = {rx0.x, rx0.y, rx0.z, rx0.w, rx1.x, rx1.y, rx1.z, rx1.w};
            #pragma unroll
            for (int i = 0; i < 8; i++) xs[bb ^ 1][(ld0 + i) * 68 + ln] = vx[i];
            *(float4*)&ws[bb ^ 1][wd * 32 + wc] = rw;
            __syncthreads();
        }
    }

    const int kcol = cb + 4 * w;
    #pragma unroll
    for (int q = 0; q < 4; q++) {
        float bq = __ldg(&b[kcol + q]);
        float2 o2;
        o2.x = acc[0][q] + bq;
        o2.y = acc[1][q] + bq;
        *(float2*)&g_xW[((size_t)t * K4 + kcol + q) * NB + 2 * l] = o2;
    }
}

// ---------------------------------------------------------------------------
// Init: g_h[0][j][n] = h0[n][j]; g_c = 0
// ---------------------------------------------------------------------------
__global__ void init_kernel(const float* __restrict__ h0)
{
    int idx = blockIdx.x * blockDim.x + threadIdx.x;  // 0..65535
    int j = idx >> 6;
    int n = idx & 63;
    g_h[0][idx] = h0[(size_t)n * HH + j];
    g_c[idx] = 0.0f;
}

// ---------------------------------------------------------------------------
// Persistent recurrence: all 1024 steps inside ONE kernel with a software
// grid barrier between steps (128 CTAs <= 148 SMs, occupancy 1 guaranteed
// -> all CTAs co-resident, barrier cannot deadlock).
// Per step: A[n][k] = g_xW[t][k][n] + sum_j h[j][n]*Wh[j][k]; gates; c,h update.
// CTA owns 8 h-columns across all 4 gates; warp = one h-column.
// ---------------------------------------------------------------------------
__global__ __launch_bounds__(256, 1) void recurrence_kernel(
    const float* __restrict__ Wh, float* __restrict__ out)
{
    const int jb = blockIdx.x * 8;

    __shared__ float hs[2][32 * 68];  // [buf][jj*68 + n]
    __shared__ float ws[2][32 * 32];  // [buf][jj*32 + col*4 + gate]

    const int tid = threadIdx.x;
    const int w = tid >> 5;
    const int l = tid & 31;

    // h loader: (j = hj, n = hn..hn+7)
    const int hj = tid >> 3;
    const int hn = (tid & 7) * 8;
    // Wh loader: (j = wk, gate = wq, local col base = wj4)
    const int wk  = tid >> 3;
    const int wq  = (tid & 7) >> 1;
    const int wj4 = (tid & 1) * 4;
    const float* wp0 = Wh + (size_t)wk * K4 + wq * HH + jb + wj4;

    // barrier generation base (monotonic across graph replays)
    unsigned int gen0 = *(volatile unsigned int*)&g_bar_gen;

    for (int t = 0; t < TT; t++) {
        const float* __restrict__ hbuf = g_h[t & 1];
        float* __restrict__ hout = g_h[(t + 1) & 1];

        float acc[2][4] = {{0.f,0.f,0.f,0.f},{0.f,0.f,0.f,0.f}};

        float4 rh0, rh1, rw;
        rh0 = *(const float4*)&hbuf[hj * NB + hn];
        rh1 = *(const float4*)&hbuf[hj * NB + hn + 4];
        rw  = *(const float4*)(wp0);
        {
            *(float4*)&hs[0][hj * 68 + hn]     = rh0;
            *(float4*)&hs[0][hj * 68 + hn + 4] = rh1;
            float vw[4] = {rw.x, rw.y, rw.z, rw.w};
            #pragma unroll
            for (int i = 0; i < 4; i++) ws[0][wk * 32 + (wj4 + i) * 4 + wq] = vw[i];
        }
        __syncthreads();

        for (int c = 0; c < 32; c++) {
            const int bb = c & 1;
            if (c < 31) {
                rh0 = *(const float4*)&hbuf[((c + 1) * 32 + hj) * NB + hn];
                rh1 = *(const float4*)&hbuf[((c + 1) * 32 + hj) * NB + hn + 4];
                rw  = *(const float4*)(wp0 + (size_t)(c + 1) * 32 * K4);
            }
            #pragma unroll
            for (int kk = 0; kk < 32; kk++) {
                float2 hv = *(const float2*)&hs[bb][kk * 68 + 2 * l];
                float4 wv = *(const float4*)&ws[bb][kk * 32 + 4 * w];
                acc[0][0] += hv.x * wv.x; acc[0][1] += hv.x * wv.y;
                acc[0][2] += hv.x * wv.z; acc[0][3] += hv.x * wv.w;
                acc[1][0] += hv.y * wv.x; acc[1][1] += hv.y * wv.y;
                acc[1][2] += hv.y * wv.z; acc[1][3] += hv.y * wv.w;
            }
            if (c < 31) {
                __syncthreads();
                *(float4*)&hs[bb ^ 1][hj * 68 + hn]     = rh0;
                *(float4*)&hs[bb ^ 1][hj * 68 + hn + 4] = rh1;
                float vw[4] = {rw.x, rw.y, rw.z, rw.w};
                #pragma unroll
                for (int i = 0; i < 4; i++) ws[bb ^ 1][wk * 32 + (wj4 + i) * 4 + wq] = vw[i];
                __syncthreads();
            }
        }

        // ---------------- fused gate epilogue ----------------
        const int jh = jb + w;            // global h column for this warp
        float2 xw[4];
        #pragma unroll
        for (int q = 0; q < 4; q++)
            xw[q] = *(const float2*)&g_xW[((size_t)t * K4 + q * HH + jh) * NB + 2 * l];

        const int cidx = jh * NB + 2 * l;
        float2 cold = *(const float2*)&g_c[cidx];

        float cv[2], hv2[2];
        #pragma unroll
        for (int r = 0; r < 2; r++) {
            float ai = acc[r][0] + (r ? xw[0].y : xw[0].x);
            float af = acc[r][1] + (r ? xw[1].y : xw[1].x);
            float ao = acc[r][2] + (r ? xw[2].y : xw[2].x);
            float ag = acc[r][3] + (r ? xw[3].y : xw[3].x);
            float ig = sigmoidf_(ai);
            float fg = sigmoidf_(af);
            float og = sigmoidf_(ao);
            float gg = tanhf(ag);
            float co = r ? cold.y : cold.x;
            float cn = fg * co + ig * gg;
            cv[r]  = cn;
            hv2[r] = og * tanhf(cn);
        }

        *(float2*)&g_c[cidx] = make_float2(cv[0], cv[1]);
        *(float2*)&hout[cidx] = make_float2(hv2[0], hv2[1]);

        // out[n][t][jh]
        out[(size_t)(2 * l) * TT * HH + (size_t)t * HH + jh]     = hv2[0];
        out[(size_t)(2 * l + 1) * TT * HH + (size_t)t * HH + jh] = hv2[1];

        // ---------------- grid-wide barrier ----------------
        __syncthreads();
        if (tid == 0) {
            __threadfence();   // publish h/c writes
            unsigned int ticket = atomicAdd(&g_bar_count, 1);
            if (ticket == NCTA - 1) {
                g_bar_count = 0;
                __threadfence();
                atomicAdd(&g_bar_gen, 1);   // release
            } else {
                while (*(volatile unsigned int*)&g_bar_gen < gen0 + (unsigned)(t + 1)) { }
            }
            __threadfence();   // acquire: h/c writes of others visible
        }
        __syncthreads();
    }
}

// ---------------------------------------------------------------------------
extern "C" void kernel_launch(void* const* d_in, const int* in_sizes, int n_in,
                              void* d_out, int out_size)
{
    (void)in_sizes; (void)n_in; (void)out_size;
    const float* x  = (const float*)d_in[0];
    const float* h0 = (const float*)d_in[1];
    const float* Wx = (const float*)d_in[2];
    const float* Wh = (const float*)d_in[3];
    const float* b  = (const float*)d_in[4];
    float* out = (float*)d_out;

    // Input projection for all timesteps (big parallel GEMM)
    phase1_kernel<<<dim3(128, 1024), 256>>>(x, Wx, b);
    // State init
    init_kernel<<<256, 256>>>(h0);
    // All 1024 recurrent steps in one persistent kernel (3-node graph total)
    recurrence_kernel<<<NCTA, 256>>>(Wh, out);
}

// round 3
// speedup vs baseline: 1.6256x; 1.6256x over previous
#include <cuda_runtime.h>
#include <math.h>

#define NB 64
#define TT 1024
#define DD 1024
#define HH 1024
#define K4 4096
#define NCTA 128

// Scratch (device globals: no allocations allowed in kernel_launch)
__device__ float g_xW[(size_t)TT * K4 * NB];   // [t][k][n], 1 GiB
__device__ float g_h[2][HH * NB];              // ping-pong [buf][j][n]
__device__ float g_c[HH * NB];                 // [j][n]

// global barrier state
__device__ unsigned int g_bar_count;
__device__ unsigned int g_bar_gen;

__device__ __forceinline__ float sigmoidf_(float v) {
    return 1.0f / (1.0f + expf(-v));
}

// ---------------------------------------------------------------------------
// Phase 1: g_xW[t][k][n] = sum_d x[n][t][d] * Wx[d][k] + b[k]
// ---------------------------------------------------------------------------
__global__ __launch_bounds__(256, 2) void phase1_kernel(
    const float* __restrict__ x, const float* __restrict__ Wx,
    const float* __restrict__ b)
{
    const int cb = blockIdx.x * 32;   // column block (k)
    const int t  = blockIdx.y;

    __shared__ float xs[2][32 * 68];  // [buf][dd*68 + n]  (transposed x tile)
    __shared__ float ws[2][32 * 32];  // [buf][dd*32 + cc]

    const int tid = threadIdx.x;
    const int w = tid >> 5;
    const int l = tid & 31;

    const int ln  = tid >> 2;
    const int ld0 = (tid & 3) * 8;
    const float* xp = x + ((size_t)ln * TT + t) * DD + ld0;

    const int wd = tid >> 3;
    const int wc = (tid & 7) * 4;
    const float* wp = Wx + (size_t)wd * K4 + cb + wc;

    float acc[2][4] = {{0.f,0.f,0.f,0.f},{0.f,0.f,0.f,0.f}};

    float4 rx0, rx1, rw;
    rx0 = *(const float4*)(xp);
    rx1 = *(const float4*)(xp + 4);
    rw  = *(const float4*)(wp);
    {
        float vx[8] = {rx0.x, rx0.y, rx0.z, rx0.w, rx1.x, rx1.y, rx1.z, rx1.w};
        #pragma unroll
        for (int i = 0; i < 8; i++) xs[0][(ld0 + i) * 68 + ln] = vx[i];
        *(float4*)&ws[0][wd * 32 + wc] = rw;
    }
    __syncthreads();

    for (int c = 0; c < 32; c++) {
        const int bb = c & 1;
        if (c < 31) {
            rx0 = *(const float4*)(xp + (c + 1) * 32);
            rx1 = *(const float4*)(xp + (c + 1) * 32 + 4);
            rw  = *(const float4*)(wp + (size_t)(c + 1) * 32 * K4);
        }
        #pragma unroll
        for (int kk = 0; kk < 32; kk++) {
            float2 hv = *(const float2*)&xs[bb][kk * 68 + 2 * l];
            float4 wv = *(const float4*)&ws[bb][kk * 32 + 4 * w];
            acc[0][0] += hv.x * wv.x; acc[0][1] += hv.x * wv.y;
            acc[0][2] += hv.x * wv.z; acc[0][3] += hv.x * wv.w;
            acc[1][0] += hv.y * wv.x; acc[1][1] += hv.y * wv.y;
            acc[1][2] += hv.y * wv.z; acc[1][3] += hv.y * wv.w;
        }
        if (c < 31) {
            __syncthreads();
            float vx[8] = {rx0.x, rx0.y, rx0.z, rx0.w, rx1.x, rx1.y, rx1.z, rx1.w};
            #pragma unroll
            for (int i = 0; i < 8; i++) xs[bb ^ 1][(ld0 + i) * 68 + ln] = vx[i];
            *(float4*)&ws[bb ^ 1][wd * 32 + wc] = rw;
            __syncthreads();
        }
    }

    const int kcol = cb + 4 * w;
    #pragma unroll
    for (int q = 0; q < 4; q++) {
        float bq = __ldg(&b[kcol + q]);
        float2 o2;
        o2.x = acc[0][q] + bq;
        o2.y = acc[1][q] + bq;
        *(float2*)&g_xW[((size_t)t * K4 + kcol + q) * NB + 2 * l] = o2;
    }
}

// ---------------------------------------------------------------------------
// Init: g_h[0][j][n] = h0[n][j]; g_c = 0
// ---------------------------------------------------------------------------
__global__ void init_kernel(const float* __restrict__ h0)
{
    int idx = blockIdx.x * blockDim.x + threadIdx.x;  // 0..65535
    int j = idx >> 6;
    int n = idx & 63;
    g_h[0][idx] = h0[(size_t)n * HH + j];
    g_c[idx] = 0.0f;
}

// ---------------------------------------------------------------------------
// Persistent recurrence: all 1024 steps inside ONE kernel with a software
// grid barrier between steps (128 CTAs <= 148 SMs, occupancy 1 guaranteed
// -> all CTAs co-resident, barrier cannot deadlock).
// Per step: A[n][k] = g_xW[t][k][n] + sum_j h[j][n]*Wh[j][k]; gates; c,h update.
// CTA owns 8 h-columns across all 4 gates; warp = one h-column.
// ---------------------------------------------------------------------------
__global__ __launch_bounds__(256, 1) void recurrence_kernel(
    const float* __restrict__ Wh, float* __restrict__ out)
{
    const int jb = blockIdx.x * 8;

    __shared__ float hs[2][32 * 68];  // [buf][jj*68 + n]
    __shared__ float ws[2][32 * 32];  // [buf][jj*32 + col*4 + gate]

    const int tid = threadIdx.x;
    const int w = tid >> 5;
    const int l = tid & 31;

    // h loader: (j = hj, n = hn..hn+7)
    const int hj = tid >> 3;
    const int hn = (tid & 7) * 8;
    // Wh loader: (j = wk, gate = wq, local col base = wj4)
    const int wk  = tid >> 3;
    const int wq  = (tid & 7) >> 1;
    const int wj4 = (tid & 1) * 4;
    const float* wp0 = Wh + (size_t)wk * K4 + wq * HH + jb + wj4;

    // barrier generation base (monotonic across graph replays)
    unsigned int gen0 = *(volatile unsigned int*)&g_bar_gen;

    for (int t = 0; t < TT; t++) {
        const float* __restrict__ hbuf = g_h[t & 1];
        float* __restrict__ hout = g_h[(t + 1) & 1];

        float acc[2][4] = {{0.f,0.f,0.f,0.f},{0.f,0.f,0.f,0.f}};

        float4 rh0, rh1, rw;
        rh0 = *(const float4*)&hbuf[hj * NB + hn];
        rh1 = *(const float4*)&hbuf[hj * NB + hn + 4];
        rw  = *(const float4*)(wp0);
        {
            *(float4*)&hs[0][hj * 68 + hn]     = rh0;
            *(float4*)&hs[0][hj * 68 + hn + 4] = rh1;
            float vw[4] = {rw.x, rw.y, rw.z, rw.w};
            #pragma unroll
            for (int i = 0; i < 4; i++) ws[0][wk * 32 + (wj4 + i) * 4 + wq] = vw[i];
        }
        __syncthreads();

        for (int c = 0; c < 32; c++) {
            const int bb = c & 1;
            if (c < 31) {
                rh0 = *(const float4*)&hbuf[((c + 1) * 32 + hj) * NB + hn];
                rh1 = *(const float4*)&hbuf[((c + 1) * 32 + hj) * NB + hn + 4];
                rw  = *(const float4*)(wp0 + (size_t)(c + 1) * 32 * K4);
            }
            #pragma unroll
            for (int kk = 0; kk < 32; kk++) {
                float2 hv = *(const float2*)&hs[bb][kk * 68 + 2 * l];
                float4 wv = *(const float4*)&ws[bb][kk * 32 + 4 * w];
                acc[0][0] += hv.x * wv.x; acc[0][1] += hv.x * wv.y;
                acc[0][2] += hv.x * wv.z; acc[0][3] += hv.x * wv.w;
                acc[1][0] += hv.y * wv.x; acc[1][1] += hv.y * wv.y;
                acc[1][2] += hv.y * wv.z; acc[1][3] += hv.y * wv.w;
            }
            if (c < 31) {
                __syncthreads();
                *(float4*)&hs[bb ^ 1][hj * 68 + hn]     = rh0;
                *(float4*)&hs[bb ^ 1][hj * 68 + hn + 4] = rh1;
                float vw[4] = {rw.x, rw.y, rw.z, rw.w};
                #pragma unroll
                for (int i = 0; i < 4; i++) ws[bb ^ 1][wk * 32 + (wj4 + i) * 4 + wq] = vw[i];
                __syncthreads();
            }
        }

        // ---------------- fused gate epilogue ----------------
        const int jh = jb + w;            // global h column for this warp
        float2 xw[4];
        #pragma unroll
        for (int q = 0; q < 4; q++)
            xw[q] = *(const float2*)&g_xW[((size_t)t * K4 + q * HH + jh) * NB + 2 * l];

        const int cidx = jh * NB + 2 * l;
        float2 cold = *(const float2*)&g_c[cidx];

        float cv[2], hv2[2];
        #pragma unroll
        for (int r = 0; r < 2; r++) {
            float ai = acc[r][0] + (r ? xw[0].y : xw[0].x);
            float af = acc[r][1] + (r ? xw[1].y : xw[1].x);
            float ao = acc[r][2] + (r ? xw[2].y : xw[2].x);
            float ag = acc[r][3] + (r ? xw[3].y : xw[3].x);
            float ig = sigmoidf_(ai);
            float fg = sigmoidf_(af);
            float og = sigmoidf_(ao);
            float gg = tanhf(ag);
            float co = r ? cold.y : cold.x;
            float cn = fg * co + ig * gg;
            cv[r]  = cn;
            hv2[r] = og * tanhf(cn);
        }

        *(float2*)&g_c[cidx] = make_float2(cv[0], cv[1]);
        *(float2*)&hout[cidx] = make_float2(hv2[0], hv2[1]);

        // out[n][t][jh]
        out[(size_t)(2 * l) * TT * HH + (size_t)t * HH + jh]     = hv2[0];
        out[(size_t)(2 * l + 1) * TT * HH + (size_t)t * HH + jh] = hv2[1];

        // ---------------- grid-wide barrier ----------------
        __syncthreads();
        if (tid == 0) {
            __threadfence();   // publish h/c writes
            unsigned int ticket = atomicAdd(&g_bar_count, 1);
            if (ticket == NCTA - 1) {
                g_bar_count = 0;
                __threadfence();
                atomicAdd(&g_bar_gen, 1);   // release
            } else {
                while (*(volatile unsigned int*)&g_bar_gen < gen0 + (unsigned)(t + 1)) { }
            }
            __threadfence();   // acquire: h/c writes of others visible
        }
        __syncthreads();
    }
}

// ---------------------------------------------------------------------------
extern "C" void kernel_launch(void* const* d_in, const int* in_sizes, int n_in,
                              void* d_out, int out_size)
{
    (void)in_sizes; (void)n_in; (void)out_size;
    const float* x  = (const float*)d_in[0];
    const float* h0 = (const float*)d_in[1];
    const float* Wx = (const float*)d_in[2];
    const float* Wh = (const float*)d_in[3];
    const float* b  = (const float*)d_in[4];
    float* out = (float*)d_out;

    // Input projection for all timesteps (big parallel GEMM)
    phase1_kernel<<<dim3(128, 1024), 256>>>(x, Wx, b);
    // State init
    init_kernel<<<256, 256>>>(h0);
    // All 1024 recurrent steps in one persistent kernel (3-node graph total)
    recurrence_kernel<<<NCTA, 256>>>(Wh, out);
}

// round 9
// speedup vs baseline: 3.2590x; 2.0048x over previous
#include <cuda_runtime.h>
#include <cuda_bf16.h>
#include <mma.h>
#include <math.h>
#include <stdint.h>

using namespace nvcuda;

#define NB 64
#define TT 1024
#define DD 1024
#define HH 1024
#define K4 4096
#define NCTA_REC 128
#define KC 64          // K-chunk (elements)
#define PE 72          // smem pitch for bf16 tiles (elements)
#define GP 68          // smem pitch for fp32 staging (elements)

// ---------------- device globals ----------------
__device__ float g_xW[(size_t)TT * K4 * NB];          // [t][k'][n]
__device__ __nv_bfloat16 g_WhT_hi[(size_t)K4 * HH];   // [k'][j]
__device__ __nv_bfloat16 g_WhT_lo[(size_t)K4 * HH];
__device__ __nv_bfloat16 g_WxT_hi[(size_t)K4 * DD];   // [k'][d]
__device__ __nv_bfloat16 g_WxT_lo[(size_t)K4 * DD];
__device__ __nv_bfloat16 g_xh[(size_t)NB * TT * DD];  // [n][t][d]
__device__ __nv_bfloat16 g_xl[(size_t)NB * TT * DD];
__device__ __nv_bfloat16 g_hh[2][(size_t)NB * HH];    // [buf][n][j]
__device__ __nv_bfloat16 g_hl[2][(size_t)NB * HH];
__device__ unsigned int g_bar_count;
__device__ unsigned int g_bar_gen;

__device__ __forceinline__ float sigf(float v) { return 1.0f / (1.0f + __expf(-v)); }

// ---------------------------------------------------------------------------
// Preps
// ---------------------------------------------------------------------------
__global__ void xsplit_kernel(const float* __restrict__ x) {
    size_t i = (size_t)blockIdx.x * 256 + threadIdx.x;   // 64M
    float v = x[i];
    __nv_bfloat16 h = __float2bfloat16(v);
    g_xh[i] = h;
    g_xl[i] = __float2bfloat16(v - __bfloat162float(h));
}

// W[j][k] (1024 x 4096) -> WT_hi/lo[k'][j], k' = (jout>>3)*32 + gate*8 + (jout&7)
// which = 0 -> g_WxT_*, which = 1 -> g_WhT_*  (destination resolved in DEVICE
// code; passing __device__ symbols from host was the R5-R8 zero-output bug)
__global__ void wprep_kernel(const float* __restrict__ W, int which) {
    __nv_bfloat16* __restrict__ dhi = which ? g_WhT_hi : g_WxT_hi;
    __nv_bfloat16* __restrict__ dlo = which ? g_WhT_lo : g_WxT_lo;
    const int k0 = blockIdx.x * 32;
    const int j0 = blockIdx.y * 32;
    __shared__ float tile[32][33];
    const int tid = threadIdx.x;
    const int jj = tid >> 5, kk = tid & 31;
    #pragma unroll
    for (int p = 0; p < 4; p++)
        tile[jj + 8 * p][kk] = W[(size_t)(j0 + jj + 8 * p) * K4 + k0 + kk];
    __syncthreads();
    const int r = tid >> 3, j4 = (tid & 7) * 4;
    const int korig = k0 + r;
    const int gate = korig >> 10, jout = korig & 1023;
    const int kp = (jout >> 3) * 32 + gate * 8 + (jout & 7);
    __nv_bfloat16 hi4[4], lo4[4];
    #pragma unroll
    for (int u = 0; u < 4; u++) {
        float v = tile[j4 + u][r];
        __nv_bfloat16 h = __float2bfloat16(v);
        hi4[u] = h;
        lo4[u] = __float2bfloat16(v - __bfloat162float(h));
    }
    size_t o = (size_t)kp * HH + j0 + j4;
    *(uint2*)&dhi[o] = *(uint2*)hi4;
    *(uint2*)&dlo[o] = *(uint2*)lo4;
}

__global__ void init_kernel(const float* __restrict__ h0) {
    int i = blockIdx.x * 256 + threadIdx.x;   // 65536, [n][j]
    float v = h0[i];
    __nv_bfloat16 h = __float2bfloat16(v);
    g_hh[0][i] = h;
    g_hl[0][i] = __float2bfloat16(v - __bfloat162float(h));
    if (i == 0) { g_bar_count = 0; g_bar_gen = 0; }
}

// ---------------------------------------------------------------------------
// Shared GEMM inner machinery (wmma; compiler owns fragment layouts).
// CTA tile: 32 k'-rows (m) x 64 n. Warps 2(m) x 4(n), each m16 x n16.
// 3-term bf16 split: Ah*Bh + Al*Bh + Ah*Bl, fp32 accumulate.
// ---------------------------------------------------------------------------
#define WMMA_COMPUTE(sAh_, sAl_, sBh_, sBl_, facc_)                              \
    _Pragma("unroll")                                                            \
    for (int ks = 0; ks < 4; ks++) {                                             \
        wmma::fragment<wmma::matrix_a, 16, 16, 16, __nv_bfloat16, wmma::row_major> fah, fal; \
        wmma::fragment<wmma::matrix_b, 16, 16, 16, __nv_bfloat16, wmma::col_major> fbh, fbl; \
        wmma::load_matrix_sync(fah, sAh_ + wm * 16 * PE + ks * 16, PE);          \
        wmma::load_matrix_sync(fal, sAl_ + wm * 16 * PE + ks * 16, PE);          \
        wmma::load_matrix_sync(fbh, sBh_ + wn * 16 * PE + ks * 16, PE);          \
        wmma::load_matrix_sync(fbl, sBl_ + wn * 16 * PE + ks * 16, PE);          \
        wmma::mma_sync(facc_, fah, fbh, facc_);                                  \
        wmma::mma_sync(facc_, fal, fbh, facc_);                                  \
        wmma::mma_sync(facc_, fah, fbl, facc_);                                  \
    }

// ---------------------------------------------------------------------------
// Phase 1: g_xW[t][k'][n] = x @ Wx + b
// ---------------------------------------------------------------------------
__global__ __launch_bounds__(256) void phase1_wmma(const float* __restrict__ b) {
    __shared__ __nv_bfloat16 sAh[32 * PE], sAl[32 * PE];
    __shared__ __nv_bfloat16 sBh[64 * PE], sBl[64 * PE];
    __shared__ float ssm[32 * GP];
    const int tid = threadIdx.x;
    const int w = tid >> 5, wm = w >> 2, wn = w & 3;
    const int cta = blockIdx.x;       // k' block (0..127)
    const int t = blockIdx.y;

    // loader mapping: A: (row=tid>>3, seg=tid&7); B: rows arow and arow+32
    const int arow = tid >> 3, aseg = tid & 7;
    const __nv_bfloat16* aph = g_WxT_hi + (size_t)(cta * 32 + arow) * DD + aseg * 8;
    const __nv_bfloat16* apl = g_WxT_lo + (size_t)(cta * 32 + arow) * DD + aseg * 8;
    const __nv_bfloat16* bph = g_xh + ((size_t)arow * TT + t) * DD + aseg * 8;
    const __nv_bfloat16* bpl = g_xl + ((size_t)arow * TT + t) * DD + aseg * 8;
    const size_t brs = (size_t)32 * TT * DD;    // +32 n rows
    const int sA = arow * PE + aseg * 8;
    const int sB0 = arow * PE + aseg * 8;
    const int sB1 = (arow + 32) * PE + aseg * 8;

    wmma::fragment<wmma::accumulator, 16, 16, 16, float> facc;
    wmma::fill_fragment(facc, 0.0f);

    uint4 rAh, rAl, rBh0, rBh1, rBl0, rBl1;
    rAh = *(const uint4*)(aph);        rAl = *(const uint4*)(apl);
    rBh0 = *(const uint4*)(bph);       rBh1 = *(const uint4*)(bph + brs);
    rBl0 = *(const uint4*)(bpl);       rBl1 = *(const uint4*)(bpl + brs);

    for (int c = 0; c < 16; c++) {
        __syncthreads();
        *(uint4*)&sAh[sA] = rAh;   *(uint4*)&sAl[sA] = rAl;
        *(uint4*)&sBh[sB0] = rBh0; *(uint4*)&sBh[sB1] = rBh1;
        *(uint4*)&sBl[sB0] = rBl0; *(uint4*)&sBl[sB1] = rBl1;
        __syncthreads();
        if (c < 15) {
            const int o = (c + 1) * KC;
            rAh = *(const uint4*)(aph + o);        rAl = *(const uint4*)(apl + o);
            rBh0 = *(const uint4*)(bph + o);       rBh1 = *(const uint4*)(bph + brs + o);
            rBl0 = *(const uint4*)(bpl + o);       rBl1 = *(const uint4*)(bpl + brs + o);
        }
        WMMA_COMPUTE(sAh, sAl, sBh, sBl, facc)
    }

    wmma::store_matrix_sync(ssm + wm * 16 * GP + wn * 16, facc, GP, wmma::mem_row_major);
    __syncthreads();

    float* xwo = g_xW + ((size_t)t * K4 + cta * 32) * 64;
    #pragma unroll
    for (int u = 0; u < 8; u++) {
        const int idx = tid + 256 * u;
        const int lm = idx >> 6, n = idx & 63;
        const int korig = (lm >> 3) * 1024 + cta * 8 + (lm & 7);
        xwo[idx] = ssm[lm * GP + n] + __ldg(&b[korig]);
    }
}

// ---------------------------------------------------------------------------
// Persistent recurrence (wmma). 128 CTAs, grid barrier per step.
// ---------------------------------------------------------------------------
__global__ __launch_bounds__(256, 1) void rec_wmma(float* __restrict__ out) {
    __shared__ __nv_bfloat16 sAh[32 * PE], sAl[32 * PE];
    __shared__ __nv_bfloat16 sBh[64 * PE], sBl[64 * PE];
    __shared__ float gsm[32 * GP];
    __shared__ float csm[8 * GP];
    const int tid = threadIdx.x;
    const int w = tid >> 5, wm = w >> 2, wn = w & 3;
    const int cta = blockIdx.x;

    const int arow = tid >> 3, aseg = tid & 7;
    const __nv_bfloat16* aph = g_WhT_hi + (size_t)(cta * 32 + arow) * HH + aseg * 8;
    const __nv_bfloat16* apl = g_WhT_lo + (size_t)(cta * 32 + arow) * HH + aseg * 8;
    const size_t bo0 = (size_t)arow * HH + aseg * 8;          // n = arow
    const size_t bo1 = (size_t)(arow + 32) * HH + aseg * 8;   // n = arow+32
    const int sA = arow * PE + aseg * 8;
    const int sB0 = arow * PE + aseg * 8;
    const int sB1 = (arow + 32) * PE + aseg * 8;

    for (int i = tid; i < 8 * GP; i += 256) csm[i] = 0.f;
    __syncthreads();

    const int cn = tid >> 2;            // n for combine
    const int jp = (tid & 3) * 2;       // jl pair base

    for (int t = 0; t < TT; t++) {
        const __nv_bfloat16* hhb = g_hh[t & 1];
        const __nv_bfloat16* hlb = g_hl[t & 1];

        // prefetch xW rows for this tile (coalesced; layout [lm][n] = linear)
        const float* xwp = g_xW + ((size_t)t * K4 + cta * 32) * 64;
        float xwr[8];
        #pragma unroll
        for (int u = 0; u < 8; u++) xwr[u] = __ldg(&xwp[tid + 256 * u]);

        wmma::fragment<wmma::accumulator, 16, 16, 16, float> facc;
        wmma::fill_fragment(facc, 0.0f);

        uint4 rAh, rAl, rBh0, rBh1, rBl0, rBl1;
        rAh = *(const uint4*)(aph);            rAl = *(const uint4*)(apl);
        rBh0 = *(const uint4*)(hhb + bo0);     rBh1 = *(const uint4*)(hhb + bo1);
        rBl0 = *(const uint4*)(hlb + bo0);     rBl1 = *(const uint4*)(hlb + bo1);

        for (int c = 0; c < 16; c++) {
            __syncthreads();
            *(uint4*)&sAh[sA] = rAh;   *(uint4*)&sAl[sA] = rAl;
            *(uint4*)&sBh[sB0] = rBh0; *(uint4*)&sBh[sB1] = rBh1;
            *(uint4*)&sBl[sB0] = rBl0; *(uint4*)&sBl[sB1] = rBl1;
            __syncthreads();
            if (c < 15) {
                const int o = (c + 1) * KC;
                rAh = *(const uint4*)(aph + o);            rAl = *(const uint4*)(apl + o);
                rBh0 = *(const uint4*)(hhb + bo0 + o);     rBh1 = *(const uint4*)(hhb + bo1 + o);
                rBl0 = *(const uint4*)(hlb + bo0 + o);     rBl1 = *(const uint4*)(hlb + bo1 + o);
            }
            WMMA_COMPUTE(sAh, sAl, sBh, sBl, facc)
        }

        wmma::store_matrix_sync(gsm + wm * 16 * GP + wn * 16, facc, GP, wmma::mem_row_major);
        __syncthreads();

        // activation pass: lm = gate*8 + jl; gate 3 (lm>=24) uses tanh
        #pragma unroll
        for (int u = 0; u < 8; u++) {
            const int idx = tid + 256 * u;
            const int lm = idx >> 6, n = idx & 63;
            const float v = gsm[lm * GP + n] + xwr[u];
            gsm[lm * GP + n] = (lm >= 24) ? tanhf(v) : sigf(v);
        }
        __syncthreads();

        // combine: thread -> (n = cn, jl in {jp, jp+1})
        float hv[2];
        __nv_bfloat16 hh2[2], hl2[2];
        #pragma unroll
        for (int u = 0; u < 2; u++) {
            const int jl = jp + u;
            const float iv = gsm[(jl)      * GP + cn];
            const float fv = gsm[(8 + jl)  * GP + cn];
            const float ov = gsm[(16 + jl) * GP + cn];
            const float gv = gsm[(24 + jl) * GP + cn];
            const float cprev = csm[jl * GP + cn];
            const float cnew = fv * cprev + iv * gv;
            csm[jl * GP + cn] = cnew;
            const float h = ov * tanhf(cnew);
            hv[u] = h;
            const __nv_bfloat16 hb = __float2bfloat16(h);
            hh2[u] = hb;
            hl2[u] = __float2bfloat16(h - __bfloat162float(hb));
        }
        *(float2*)&out[((size_t)cn * TT + t) * HH + cta * 8 + jp] = make_float2(hv[0], hv[1]);
        const int nb = (t + 1) & 1;
        *(uint32_t*)&g_hh[nb][(size_t)cn * HH + cta * 8 + jp] = *(uint32_t*)hh2;
        *(uint32_t*)&g_hl[nb][(size_t)cn * HH + cta * 8 + jp] = *(uint32_t*)hl2;

        // grid barrier (128 CTAs, 1/SM, co-resident)
        __syncthreads();
        if (tid == 0) {
            __threadfence();
            unsigned int ticket = atomicAdd(&g_bar_count, 1);
            if (ticket == NCTA_REC - 1) {
                g_bar_count = 0;
                __threadfence();
                atomicAdd(&g_bar_gen, 1);
            } else {
                while (*(volatile unsigned int*)&g_bar_gen < (unsigned)(t + 1)) { }
            }
            __threadfence();
        }
        __syncthreads();
    }
}

// ---------------------------------------------------------------------------
extern "C" void kernel_launch(void* const* d_in, const int* in_sizes, int n_in,
                              void* d_out, int out_size)
{
    (void)in_sizes; (void)n_in; (void)out_size;
    const float* x  = (const float*)d_in[0];
    const float* h0 = (const float*)d_in[1];
    const float* Wx = (const float*)d_in[2];
    const float* Wh = (const float*)d_in[3];
    const float* b  = (const float*)d_in[4];
    float* out = (float*)d_out;

    xsplit_kernel<<<262144, 256>>>(x);
    wprep_kernel<<<dim3(128, 32), 256>>>(Wx, 0);   // -> g_WxT_hi/lo
    wprep_kernel<<<dim3(128, 32), 256>>>(Wh, 1);   // -> g_WhT_hi/lo
    init_kernel<<<256, 256>>>(h0);
    phase1_wmma<<<dim3(128, 1024), 256>>>(b);
    rec_wmma<<<NCTA_REC, 256>>>(out);
}